// round 5
// baseline (speedup 1.0000x reference)
#include <cuda_runtime.h>
#include <cuda_fp16.h>
#include <cstdint>
#include <math.h>

#define Bn 256
#define Tn 4096
#define BT (Bn*Tn)

__device__ unsigned g_h [BT];   // GRU hidden half2

static __device__ __forceinline__ __half2 tanh2(__half2 x){
    unsigned xi = *reinterpret_cast<unsigned*>(&x), ri;
    asm("tanh.approx.f16x2 %0, %1;" : "=r"(ri) : "r"(xi));
    return *reinterpret_cast<__half2*>(&ri);
}
static __device__ __forceinline__ float tanhap(float x){
    float y; asm("tanh.approx.f32 %0, %1;" : "=f"(y) : "f"(x)); return y;
}

// ============== K1: GRU, fused input gates, 32-step chunks ==============
__global__ __launch_bounds__(128) void gru_kernel(
    const float* __restrict__ x,
    const float* __restrict__ wih, const float* __restrict__ whh,
    const float* __restrict__ bih, const float* __restrict__ bhh)
{
    int gid = blockIdx.x*128 + threadIdx.x;   // 32768 = 256 b * 128 chunks
    int b = gid >> 7, c = gid & 127;

    // input-gate weights: rows r,z pre-halved; biases folded (r,z get +bhh, halved)
    float WI[18], CB[6];
#pragma unroll
    for (int j=0;j<4;j++){
#pragma unroll
        for (int d=0;d<3;d++) WI[j*3+d] = 0.5f*wih[j*3+d];
        CB[j] = 0.5f*(bih[j]+bhh[j]);
    }
#pragma unroll
    for (int j=4;j<6;j++){
#pragma unroll
        for (int d=0;d<3;d++) WI[j*3+d] = wih[j*3+d];
        CB[j] = bih[j];
    }

    float w[12];
#pragma unroll
    for (int i=0;i<12;i++) w[i]=whh[i];
    __half2 WRA=__floats2half2_rn(0.5f*w[0],0.5f*w[2]), WRB=__floats2half2_rn(0.5f*w[1],0.5f*w[3]);
    __half2 WZA=__floats2half2_rn(0.5f*w[4],0.5f*w[6]), WZB=__floats2half2_rn(0.5f*w[5],0.5f*w[7]);
    __half2 WNA=__floats2half2_rn(w[8],w[10]),          WNB=__floats2half2_rn(w[9],w[11]);
    __half2 BN =__floats2half2_rn(bhh[4],bhh[5]);
    const __half2 H05=__floats2half2_rn(0.5f,0.5f), HM05=__floats2half2_rn(-0.5f,-0.5f);

    int t0 = c*32;
    int tstart = (c==0) ? 0 : (t0-32);
    int nwarm  = t0 - tstart;                  // 0 or 32
    const float* xp = x + ((size_t)b*Tn + tstart)*3;
    unsigned*    hp = g_h + (size_t)b*Tn + tstart;

    float ax[8], ay[8], az[8];
#pragma unroll
    for (int i=0;i<8;i++){ ax[i]=xp[i*3]; ay[i]=xp[i*3+1]; az[i]=xp[i*3+2]; }

    __half2 h = __floats2half2_rn(0.f,0.f);
    for (int s=0; s<64; s+=8) {
#pragma unroll
        for (int i=0;i<8;i++){
            float x0=ax[i], x1=ay[i], x2=az[i];
            int pf = s+i+8; pf = (pf<64)?pf:0;
            ax[i]=xp[pf*3]; ay[i]=xp[pf*3+1]; az[i]=xp[pf*3+2];

            float gr0=fmaf(WI[0],x0,fmaf(WI[1],x1,fmaf(WI[2],x2,CB[0])));
            float gr1=fmaf(WI[3],x0,fmaf(WI[4],x1,fmaf(WI[5],x2,CB[1])));
            float gz0=fmaf(WI[6],x0,fmaf(WI[7],x1,fmaf(WI[8],x2,CB[2])));
            float gz1=fmaf(WI[9],x0,fmaf(WI[10],x1,fmaf(WI[11],x2,CB[3])));
            float gn0=fmaf(WI[12],x0,fmaf(WI[13],x1,fmaf(WI[14],x2,CB[4])));
            float gn1=fmaf(WI[15],x0,fmaf(WI[16],x1,fmaf(WI[17],x2,CB[5])));
            __half2 CR=__floats2half2_rn(gr0,gr1);
            __half2 CZ=__floats2half2_rn(gz0,gz1);
            __half2 CN=__floats2half2_rn(gn0,gn1);

            __half2 h0b=__half2half2(__low2half(h)), h1b=__half2half2(__high2half(h));
            __half2 aR=__hfma2(h0b,WRA,__hfma2(h1b,WRB,CR));
            __half2 aZ=__hfma2(h0b,WZA,__hfma2(h1b,WZB,CZ));
            __half2 GN=__hfma2(h0b,WNA,__hfma2(h1b,WNB,BN));
            __half2 tr=tanh2(aR), tz=tanh2(aZ);
            __half2 Ch=__hmul2(GN,H05);
            __half2 aN=__hfma2(tr,Ch,__hadd2(CN,Ch));
            __half2 tn=tanh2(aN);
            __half2 A =__hfma2(tz,HM05,H05);
            __half2 hh=__hmul2(h,H05);
            __half2 ZH=__hfma2(tz,hh,hh);
            h = __hfma2(tn,A,ZH);

            int tt = s+i;
            if (tt>=nwarm && tt<nwarm+32) hp[tt]=*reinterpret_cast<unsigned*>(&h);
        }
    }
}

// ============== K2: emitter + HMM scan + epilogue ==============
// smem floats: sq[4096] suf svf sbu sbv [4096 ea] sSub[1024] sP[256]
//              sBfU/V sEbU/V [64 ea] = 22016 floats = 88064 B
#define HMM_SMEM 88064
__global__ __launch_bounds__(256) void hmm_kernel(
    const float* __restrict__ x,   const float* __restrict__ Qseq,
    const float* __restrict__ lpi, const float* __restrict__ lAg,
    const float* __restrict__ fc1w,const float* __restrict__ fc1b,
    const float* __restrict__ fc2w,const float* __restrict__ fc2b,
    const float* __restrict__ Wgp, const float* __restrict__ byp,
    float* __restrict__ out)
{
    extern __shared__ float sm[];
    float* sq   = sm;
    float* suf  = sm+4096;
    float* svf  = sm+8192;
    float* sbu  = sm+12288;
    float* sbv  = sm+16384;
    float* sSub = sm+20480;
    float* sP   = sm+21504;
    float* sBfU = sm+21760;
    float* sBfV = sm+21824;
    float* sEbU = sm+21888;
    float* sEbV = sm+21952;

    int b = blockIdx.x, tid = threadIdx.x;

    // stage 0: emitter -> q ratios in smem
    {
        float W1[24], B1[8], DW[8];
#pragma unroll
        for (int i=0;i<24;i++) W1[i]=fc1w[i];
#pragma unroll
        for (int i=0;i<8;i++){ B1[i]=fc1b[i]; DW[i]=fc2w[8+i]-fc2w[i]; }
        float db = fc2b[1]-fc2b[0];
        const float* xb = x + (size_t)b*Tn*3;
#pragma unroll
        for (int k=0;k<16;k++){
            int t = tid + k*256;
            float x0=xb[t*3], x1=xb[t*3+1], x2=xb[t*3+2];
            float d = db;
#pragma unroll
            for (int j=0;j<8;j++){
                float u = fmaf(W1[j*3],x0,fmaf(W1[j*3+1],x1,fmaf(W1[j*3+2],x2,B1[j])));
                d = fmaf(DW[j], tanhap(u), d);
            }
            sq[t] = __expf(d);
        }
    }

    float l00=lAg[0],l01=lAg[1],l10=lAg[2],l11=lAg[3];
    float m0=fmaxf(l00,l01), m1=fmaxf(l10,l11);
    float e00=__expf(l00-m0), e01=__expf(l01-m0), e10=__expf(l10-m1), e11=__expf(l11-m1);
    float i0=__fdividef(1.f,e00+e01), i1=__fdividef(1.f,e10+e11);
    float a00=e00*i0, a01=e01*i0, a10=e10*i1, a11=e11*i1;
    float p1=__expf(lpi[1]-lpi[0]);

    float WG[20], BY[4];
#pragma unroll
    for (int i=0;i<20;i++) WG[i]=Wgp[i];
#pragma unroll
    for (int i=0;i<4;i++) BY[i]=byp[i];
    __syncthreads();

    // stage 1a: 16-step sub-products
    {
        int ts = tid*16, te = ts+16;
        if (tid==0) ts = 1;
        float p00=1.f,p01=0.f,p10=0.f,p11=1.f;
        for (int t=ts;t<te;t++){
            float qv=sq[t], qa01=a01*qv, qa11=a11*qv;
            float n00=fmaf(p01,a10,p00*a00), n01=fmaf(p01,qa11,p00*qa01);
            float n10=fmaf(p11,a10,p10*a00), n11=fmaf(p11,qa11,p10*qa01);
            p00=n00;p01=n01;p10=n10;p11=n11;
        }
        float s=__fdividef(1.f,p00+p01+p10+p11);
        sSub[tid*4]=p00*s; sSub[tid*4+1]=p01*s; sSub[tid*4+2]=p10*s; sSub[tid*4+3]=p11*s;
    }
    __syncthreads();

    // stage 1b: combine -> chunk products
    if (tid < 64) {
        float p00=sSub[tid*16], p01=sSub[tid*16+1], p10=sSub[tid*16+2], p11=sSub[tid*16+3];
#pragma unroll
        for (int j=1;j<4;j++){
            const float* S = sSub + tid*16 + j*4;
            float n00=fmaf(p01,S[2],p00*S[0]), n01=fmaf(p01,S[3],p00*S[1]);
            float n10=fmaf(p11,S[2],p10*S[0]), n11=fmaf(p11,S[3],p10*S[1]);
            p00=n00;p01=n01;p10=n10;p11=n11;
        }
        float s=__fdividef(1.f,p00+p01+p10+p11);
        sP[tid*4]=p00*s; sP[tid*4+1]=p01*s; sP[tid*4+2]=p10*s; sP[tid*4+3]=p11*s;
    }
    __syncthreads();

    // stage 2: boundary chains
    if (tid == 0) {
        float u=1.f, v=p1*sq[0];
        sBfU[0]=u; sBfV[0]=v;
        for (int c=0;c<63;c++){
            const float* P=sP+c*4;
            float nu=fmaf(v,P[2],u*P[0]);
            float nv=fmaf(v,P[3],u*P[1]);
            u=nu; v=nv;
            if ((c&7)==7){ float is=__fdividef(1.f,u+v); u*=is; v*=is; }
            sBfU[c+1]=u; sBfV[c+1]=v;
        }
    } else if (tid == 32) {
        float u=1.f, v=1.f;
        sEbU[63]=1.f; sEbV[63]=1.f;
        for (int c=62;c>=0;c--){
            const float* P=sP+(c+1)*4;
            float nu=fmaf(P[1],v,P[0]*u);
            float nv=fmaf(P[3],v,P[2]*u);
            u=nu; v=nv;
            if ((c&7)==0){ float is=__fdividef(1.f,u+v); u*=is; v*=is; }
            sEbU[c]=u; sEbV[c]=v;
        }
    }
    __syncthreads();

    // stage 3: within-chunk replay
    if (tid < 64) {
        int c=tid;
        float u,v; int ts;
        if (c==0){ u=1.f; v=p1*sq[0]; suf[0]=u; svf[0]=v; ts=1; }
        else     { u=sBfU[c]; v=sBfV[c]; ts=c*64; }
        int te=c*64+63;
        for (int t=ts;t<=te;t++){
            float qv=sq[t];
            float nu=fmaf(a10,v,a00*u);
            float nv=qv*fmaf(a11,v,a01*u);
            u=nu; v=nv;
            if ((t&7)==7){ float is=__fdividef(1.f,u+v); u*=is; v*=is; }
            suf[t]=u; svf[t]=v;
        }
    } else if (tid < 128) {
        int c=tid-64;
        float u=sEbU[c], v=sEbV[c];
        int te=c*64+63;
        sbu[te]=u; sbv[te]=v;
        for (int t=te-1;t>=c*64;t--){
            float w=sq[t+1]*v;
            float nu=fmaf(a01,w,a00*u);
            float nv=fmaf(a11,w,a10*u);
            u=nu; v=nv;
            if ((t&7)==0){ float is=__fdividef(1.f,u+v); u*=is; v*=is; }
            sbu[t]=u; sbv[t]=v;
        }
    }
    __syncthreads();

    // stage 4: epilogue
    const size_t OFF1=(size_t)Bn*Tn*2, OFF2=(size_t)Bn*Tn*7;
    for (int t=tid; t<Tn; t+=256) {
        size_t bt=(size_t)b*Tn+t;
        float n0 = suf[t]*sbu[t];
        float n1 = svf[t]*sbv[t];
        float iden = __fdividef(1.f, n0+n1);
        float gm0 = n0*iden, gm1 = n1*iden;
        float lg0 = __logf(gm0), lg1 = __logf(gm1);

        unsigned hv=g_h[bt];
        __half2 h2=*reinterpret_cast<__half2*>(&hv);
        float h0=__low2float(h2), h1=__high2float(h2);

        float gk[2][5];
#pragma unroll
        for (int k=0;k<2;k++){
            float wv[5], mx=-1e30f;
#pragma unroll
            for (int a=0;a<5;a++){ wv[a]=fmaf(h0,WG[k*10+a],h1*WG[k*10+5+a]); mx=fmaxf(mx,wv[a]); }
            float s=0.f;
#pragma unroll
            for (int a=0;a<5;a++){ wv[a]=__expf(wv[a]-mx); s+=wv[a]; }
            float is=__fdividef(1.f,s);
#pragma unroll
            for (int a=0;a<5;a++) gk[k][a]=wv[a]*is;
        }
        float gv[5];
#pragma unroll
        for (int a=0;a<5;a++) gv[a]=fmaf(gm0,gk[0][a],gm1*gk[1][a]);

        const float2* Qp=reinterpret_cast<const float2*>(Qseq+bt*10);
        float V0=fmaf(gm0,BY[0],gm1*BY[2]);
        float V1=fmaf(gm0,BY[1],gm1*BY[3]);
#pragma unroll
        for (int a=0;a<5;a++){
            float2 qy=Qp[a];
            V0=fmaf(gv[a],qy.x,V0);
            V1=fmaf(gv[a],qy.y,V1);
        }
        float mv=fmaxf(V0,V1);
        float lse=mv+__logf(__expf(V0-mv)+__expf(V1-mv));

        out[bt*2]=V0-lse; out[bt*2+1]=V1-lse;
        float* go=out+OFF1+bt*5;
#pragma unroll
        for (int a=0;a<5;a++) go[a]=gv[a];
        out[OFF2+bt*2]=lg0; out[OFF2+bt*2+1]=lg1;
    }
}

// ========================= launch =========================
extern "C" void kernel_launch(void* const* d_in, const int* in_sizes, int n_in,
                              void* d_out, int out_size)
{
    const float* x    =(const float*)d_in[0];
    const float* Qseq =(const float*)d_in[1];
    const float* lpi  =(const float*)d_in[2];
    const float* lA   =(const float*)d_in[3];
    const float* fc1w =(const float*)d_in[4];
    const float* fc1b =(const float*)d_in[5];
    const float* fc2w =(const float*)d_in[6];
    const float* fc2b =(const float*)d_in[7];
    const float* wih  =(const float*)d_in[8];
    const float* whh  =(const float*)d_in[9];
    const float* bih  =(const float*)d_in[10];
    const float* bhh  =(const float*)d_in[11];
    const float* Wg   =(const float*)d_in[12];
    const float* by   =(const float*)d_in[13];
    float* out=(float*)d_out;

    static bool attr_set=false;
    if (!attr_set){
        cudaFuncSetAttribute(hmm_kernel, cudaFuncAttributeMaxDynamicSharedMemorySize, HMM_SMEM);
        attr_set=true;
    }

    gru_kernel<<<256,128>>>(x,wih,whh,bih,bhh);
    hmm_kernel<<<256,256,HMM_SMEM>>>(x,Qseq,lpi,lA,fc1w,fc1b,fc2w,fc2b,Wg,by,out);
}

// round 6
// speedup vs baseline: 1.1616x; 1.1616x over previous
#include <cuda_runtime.h>
#include <cuda_fp16.h>
#include <cstdint>
#include <math.h>

#define Bn 256
#define Tn 4096
#define BT (Bn*Tn)

__device__ unsigned g_h [BT];   // GRU hidden half2
__device__ float    g_gm[BT];   // gamma_1

static __device__ __forceinline__ __half2 tanh2(__half2 x){
    unsigned xi = *reinterpret_cast<unsigned*>(&x), ri;
    asm("tanh.approx.f16x2 %0, %1;" : "=r"(ri) : "r"(xi));
    return *reinterpret_cast<__half2*>(&ri);
}
static __device__ __forceinline__ float tanhap(float x){
    float y; asm("tanh.approx.f32 %0, %1;" : "=f"(y) : "f"(x)); return y;
}

// ============== K1: GRU — smem-staged gates, 32-step chunks ==============
// block = 128 thr (4 warps), 1 batch/block. warp w handles chunks 32w..32w+31.
#define GATE_WORDS 3204   // 1056*3 + pad
#define HB_WORDS   1092   // 1056 + pad
#define WARP_WORDS (GATE_WORDS + HB_WORDS)
#define GRU_SMEM   (4 * WARP_WORDS * 4)

__global__ __launch_bounds__(128) void gru_kernel(
    const float* __restrict__ x,
    const float* __restrict__ wih, const float* __restrict__ whh,
    const float* __restrict__ bih, const float* __restrict__ bhh)
{
    extern __shared__ unsigned sg[];
    int b = blockIdx.x;
    int wid = threadIdx.x >> 5, lane = threadIdx.x & 31;
    unsigned* gbuf = sg + wid * WARP_WORDS;
    unsigned* hbuf = gbuf + GATE_WORDS;

    // input-gate weights (r,z pre-halved, biases folded)
    float WI[18], CB[6];
#pragma unroll
    for (int j=0;j<4;j++){
#pragma unroll
        for (int d=0;d<3;d++) WI[j*3+d] = 0.5f*wih[j*3+d];
        CB[j] = 0.5f*(bih[j]+bhh[j]);
    }
#pragma unroll
    for (int j=4;j<6;j++){
#pragma unroll
        for (int d=0;d<3;d++) WI[j*3+d] = wih[j*3+d];
        CB[j] = bih[j];
    }
    float w[12];
#pragma unroll
    for (int i=0;i<12;i++) w[i]=whh[i];
    __half2 WRA=__floats2half2_rn(0.5f*w[0],0.5f*w[2]), WRB=__floats2half2_rn(0.5f*w[1],0.5f*w[3]);
    __half2 WZA=__floats2half2_rn(0.5f*w[4],0.5f*w[6]), WZB=__floats2half2_rn(0.5f*w[5],0.5f*w[7]);
    __half2 WNA=__floats2half2_rn(w[8],w[10]),          WNB=__floats2half2_rn(w[9],w[11]);
    __half2 BN =__floats2half2_rn(bhh[4],bhh[5]);
    const __half2 H05=__floats2half2_rn(0.5f,0.5f), HM05=__floats2half2_rn(-0.5f,-0.5f);

    int tile_base = 1024*wid - 32; if (tile_base < 0) tile_base = 0;
    int tile_len  = (wid==0) ? 1024 : 1056;
    const float* xb = x + ((size_t)b*Tn + tile_base)*3;

    // ---- stage gates into smem (parallel across lanes, coalesced x reads) ----
    for (int k=lane; k<tile_len; k+=32) {
        float x0=xb[k*3], x1=xb[k*3+1], x2=xb[k*3+2];
        float gr0=fmaf(WI[0],x0,fmaf(WI[1],x1,fmaf(WI[2],x2,CB[0])));
        float gr1=fmaf(WI[3],x0,fmaf(WI[4],x1,fmaf(WI[5],x2,CB[1])));
        float gz0=fmaf(WI[6],x0,fmaf(WI[7],x1,fmaf(WI[8],x2,CB[2])));
        float gz1=fmaf(WI[9],x0,fmaf(WI[10],x1,fmaf(WI[11],x2,CB[3])));
        float gn0=fmaf(WI[12],x0,fmaf(WI[13],x1,fmaf(WI[14],x2,CB[4])));
        float gn1=fmaf(WI[15],x0,fmaf(WI[16],x1,fmaf(WI[17],x2,CB[5])));
        __half2 CR=__floats2half2_rn(gr0,gr1);
        __half2 CZ=__floats2half2_rn(gz0,gz1);
        __half2 CN=__floats2half2_rn(gn0,gn1);
        int a = k*3 + (k>>5);
        gbuf[a]   = *reinterpret_cast<unsigned*>(&CR);
        gbuf[a+1] = *reinterpret_cast<unsigned*>(&CZ);
        gbuf[a+2] = *reinterpret_cast<unsigned*>(&CN);
    }
    __syncwarp();

    // ---- serial chain: chunk c, 32 warmup + 32 output steps ----
    int c = wid*32 + lane;
    int tstart = (c==0) ? 0 : c*32 - 32;
    int li = tstart - tile_base;
    int nwarm = (c==0) ? 0 : 32;

    __half2 h = __floats2half2_rn(0.f,0.f);
#pragma unroll 4
    for (int s=0; s<64; s++){
        int tt = li + s;
        int a = tt*3 + (tt>>5);
        unsigned u0=gbuf[a], u1=gbuf[a+1], u2=gbuf[a+2];
        __half2 CR=*reinterpret_cast<__half2*>(&u0);
        __half2 CZ=*reinterpret_cast<__half2*>(&u1);
        __half2 CN=*reinterpret_cast<__half2*>(&u2);

        __half2 h0b=__half2half2(__low2half(h)), h1b=__half2half2(__high2half(h));
        __half2 aR=__hfma2(h0b,WRA,__hfma2(h1b,WRB,CR));
        __half2 aZ=__hfma2(h0b,WZA,__hfma2(h1b,WZB,CZ));
        __half2 GN=__hfma2(h0b,WNA,__hfma2(h1b,WNB,BN));
        __half2 tr=tanh2(aR), tz=tanh2(aZ);
        __half2 Ch=__hmul2(GN,H05);
        __half2 aN=__hfma2(tr,Ch,__hadd2(CN,Ch));
        __half2 tn=tanh2(aN);
        __half2 A =__hfma2(tz,HM05,H05);
        __half2 hh=__hmul2(h,H05);
        __half2 ZH=__hfma2(tz,hh,hh);
        h = __hfma2(tn,A,ZH);

        if (s>=nwarm && s<nwarm+32)
            hbuf[tt + (tt>>5)] = *reinterpret_cast<unsigned*>(&h);
    }
    __syncwarp();

    // ---- coalesced writeback of this warp's 1024 outputs ----
    unsigned* hout = g_h + (size_t)b*Tn + 1024*wid;
    int off = wid ? 32 : 0;
    for (int u=lane; u<1024; u+=32){
        int tt = u + off;
        hout[u] = hbuf[tt + (tt>>5)];
    }
}

// ============== K2: emitter + HMM scan -> gamma1 ==============
#define HMM_SMEM 88064
__global__ __launch_bounds__(256) void hmm_kernel(
    const float* __restrict__ x,
    const float* __restrict__ lpi, const float* __restrict__ lAg,
    const float* __restrict__ fc1w,const float* __restrict__ fc1b,
    const float* __restrict__ fc2w,const float* __restrict__ fc2b)
{
    extern __shared__ float sm[];
    float* sq   = sm;
    float* suf  = sm+4096;
    float* svf  = sm+8192;
    float* sbu  = sm+12288;
    float* sbv  = sm+16384;
    float* sSub = sm+20480;
    float* sP   = sm+21504;
    float* sBfU = sm+21760;
    float* sBfV = sm+21824;
    float* sEbU = sm+21888;
    float* sEbV = sm+21952;

    int b = blockIdx.x, tid = threadIdx.x;

    // emitter -> q ratios
    {
        float W1[24], B1[8], DW[8];
#pragma unroll
        for (int i=0;i<24;i++) W1[i]=fc1w[i];
#pragma unroll
        for (int i=0;i<8;i++){ B1[i]=fc1b[i]; DW[i]=fc2w[8+i]-fc2w[i]; }
        float db = fc2b[1]-fc2b[0];
        const float* xb = x + (size_t)b*Tn*3;
#pragma unroll
        for (int k=0;k<16;k++){
            int t = tid + k*256;
            float x0=xb[t*3], x1=xb[t*3+1], x2=xb[t*3+2];
            float d = db;
#pragma unroll
            for (int j=0;j<8;j++){
                float u = fmaf(W1[j*3],x0,fmaf(W1[j*3+1],x1,fmaf(W1[j*3+2],x2,B1[j])));
                d = fmaf(DW[j], tanhap(u), d);
            }
            sq[t] = __expf(d);
        }
    }

    float l00=lAg[0],l01=lAg[1],l10=lAg[2],l11=lAg[3];
    float m0=fmaxf(l00,l01), m1=fmaxf(l10,l11);
    float e00=__expf(l00-m0), e01=__expf(l01-m0), e10=__expf(l10-m1), e11=__expf(l11-m1);
    float i0=__fdividef(1.f,e00+e01), i1=__fdividef(1.f,e10+e11);
    float a00=e00*i0, a01=e01*i0, a10=e10*i1, a11=e11*i1;
    float p1=__expf(lpi[1]-lpi[0]);
    __syncthreads();

    // 16-step sub-products
    {
        int ts = tid*16, te = ts+16;
        if (tid==0) ts = 1;
        float p00=1.f,p01=0.f,p10=0.f,p11=1.f;
        for (int t=ts;t<te;t++){
            float qv=sq[t], qa01=a01*qv, qa11=a11*qv;
            float n00=fmaf(p01,a10,p00*a00), n01=fmaf(p01,qa11,p00*qa01);
            float n10=fmaf(p11,a10,p10*a00), n11=fmaf(p11,qa11,p10*qa01);
            p00=n00;p01=n01;p10=n10;p11=n11;
        }
        float s=__fdividef(1.f,p00+p01+p10+p11);
        sSub[tid*4]=p00*s; sSub[tid*4+1]=p01*s; sSub[tid*4+2]=p10*s; sSub[tid*4+3]=p11*s;
    }
    __syncthreads();

    // combine -> 64 chunk products
    if (tid < 64) {
        float p00=sSub[tid*16], p01=sSub[tid*16+1], p10=sSub[tid*16+2], p11=sSub[tid*16+3];
#pragma unroll
        for (int j=1;j<4;j++){
            const float* S = sSub + tid*16 + j*4;
            float n00=fmaf(p01,S[2],p00*S[0]), n01=fmaf(p01,S[3],p00*S[1]);
            float n10=fmaf(p11,S[2],p10*S[0]), n11=fmaf(p11,S[3],p10*S[1]);
            p00=n00;p01=n01;p10=n10;p11=n11;
        }
        float s=__fdividef(1.f,p00+p01+p10+p11);
        sP[tid*4]=p00*s; sP[tid*4+1]=p01*s; sP[tid*4+2]=p10*s; sP[tid*4+3]=p11*s;
    }
    __syncthreads();

    // boundary chains
    if (tid == 0) {
        float u=1.f, v=p1*sq[0];
        sBfU[0]=u; sBfV[0]=v;
        for (int c=0;c<63;c++){
            const float* P=sP+c*4;
            float nu=fmaf(v,P[2],u*P[0]);
            float nv=fmaf(v,P[3],u*P[1]);
            u=nu; v=nv;
            if ((c&7)==7){ float is=__fdividef(1.f,u+v); u*=is; v*=is; }
            sBfU[c+1]=u; sBfV[c+1]=v;
        }
    } else if (tid == 32) {
        float u=1.f, v=1.f;
        sEbU[63]=1.f; sEbV[63]=1.f;
        for (int c=62;c>=0;c--){
            const float* P=sP+(c+1)*4;
            float nu=fmaf(P[1],v,P[0]*u);
            float nv=fmaf(P[3],v,P[2]*u);
            u=nu; v=nv;
            if ((c&7)==0){ float is=__fdividef(1.f,u+v); u*=is; v*=is; }
            sEbU[c]=u; sEbV[c]=v;
        }
    }
    __syncthreads();

    // within-chunk replay
    if (tid < 64) {
        int c=tid;
        float u,v; int ts;
        if (c==0){ u=1.f; v=p1*sq[0]; suf[0]=u; svf[0]=v; ts=1; }
        else     { u=sBfU[c]; v=sBfV[c]; ts=c*64; }
        int te=c*64+63;
        for (int t=ts;t<=te;t++){
            float qv=sq[t];
            float nu=fmaf(a10,v,a00*u);
            float nv=qv*fmaf(a11,v,a01*u);
            u=nu; v=nv;
            if ((t&7)==7){ float is=__fdividef(1.f,u+v); u*=is; v*=is; }
            suf[t]=u; svf[t]=v;
        }
    } else if (tid < 128) {
        int c=tid-64;
        float u=sEbU[c], v=sEbV[c];
        int te=c*64+63;
        sbu[te]=u; sbv[te]=v;
        for (int t=te-1;t>=c*64;t--){
            float w=sq[t+1]*v;
            float nu=fmaf(a01,w,a00*u);
            float nv=fmaf(a11,w,a10*u);
            u=nu; v=nv;
            if ((t&7)==0){ float is=__fdividef(1.f,u+v); u*=is; v*=is; }
            sbu[t]=u; sbv[t]=v;
        }
    }
    __syncthreads();

    // gamma1 out (coalesced)
    float* gmp = g_gm + (size_t)b*Tn;
    for (int t=tid; t<Tn; t+=256){
        float n0 = suf[t]*sbu[t];
        float n1 = svf[t]*sbv[t];
        gmp[t] = __fdividef(n1, n0+n1);
    }
}

// ============== K3: epilogue (full occupancy, no smem) ==============
__global__ __launch_bounds__(256) void epi_kernel(
    const float* __restrict__ Qseq,
    const float* __restrict__ Wgp, const float* __restrict__ byp,
    float* __restrict__ out)
{
    int idx = blockIdx.x*256 + threadIdx.x;   // = b*Tn + t
    float WG[20], BY[4];
#pragma unroll
    for (int i=0;i<20;i++) WG[i]=Wgp[i];
#pragma unroll
    for (int i=0;i<4;i++) BY[i]=byp[i];

    float gm1 = g_gm[idx], gm0 = 1.f - gm1;
    float lg0 = __logf(gm0), lg1 = __logf(gm1);

    unsigned hv = g_h[idx];
    __half2 h2 = *reinterpret_cast<__half2*>(&hv);
    float h0=__low2float(h2), h1=__high2float(h2);

    float gk[2][5];
#pragma unroll
    for (int k=0;k<2;k++){
        float wv[5], mx=-1e30f;
#pragma unroll
        for (int a=0;a<5;a++){ wv[a]=fmaf(h0,WG[k*10+a],h1*WG[k*10+5+a]); mx=fmaxf(mx,wv[a]); }
        float s=0.f;
#pragma unroll
        for (int a=0;a<5;a++){ wv[a]=__expf(wv[a]-mx); s+=wv[a]; }
        float is=__fdividef(1.f,s);
#pragma unroll
        for (int a=0;a<5;a++) gk[k][a]=wv[a]*is;
    }
    float gv[5];
#pragma unroll
    for (int a=0;a<5;a++) gv[a]=fmaf(gm0,gk[0][a],gm1*gk[1][a]);

    const float2* Qp = reinterpret_cast<const float2*>(Qseq + (size_t)idx*10);
    float V0=fmaf(gm0,BY[0],gm1*BY[2]);
    float V1=fmaf(gm0,BY[1],gm1*BY[3]);
#pragma unroll
    for (int a=0;a<5;a++){
        float2 qy=Qp[a];
        V0=fmaf(gv[a],qy.x,V0);
        V1=fmaf(gv[a],qy.y,V1);
    }
    float mv=fmaxf(V0,V1);
    float lse=mv+__logf(__expf(V0-mv)+__expf(V1-mv));

    const size_t OFF1=(size_t)BT*2, OFF2=(size_t)BT*7;
    float2* o2 = reinterpret_cast<float2*>(out + (size_t)idx*2);
    *o2 = make_float2(V0-lse, V1-lse);
    float* go = out + OFF1 + (size_t)idx*5;
#pragma unroll
    for (int a=0;a<5;a++) go[a]=gv[a];
    float2* l2 = reinterpret_cast<float2*>(out + OFF2 + (size_t)idx*2);
    *l2 = make_float2(lg0, lg1);
}

// ========================= launch =========================
extern "C" void kernel_launch(void* const* d_in, const int* in_sizes, int n_in,
                              void* d_out, int out_size)
{
    const float* x    =(const float*)d_in[0];
    const float* Qseq =(const float*)d_in[1];
    const float* lpi  =(const float*)d_in[2];
    const float* lA   =(const float*)d_in[3];
    const float* fc1w =(const float*)d_in[4];
    const float* fc1b =(const float*)d_in[5];
    const float* fc2w =(const float*)d_in[6];
    const float* fc2b =(const float*)d_in[7];
    const float* wih  =(const float*)d_in[8];
    const float* whh  =(const float*)d_in[9];
    const float* bih  =(const float*)d_in[10];
    const float* bhh  =(const float*)d_in[11];
    const float* Wg   =(const float*)d_in[12];
    const float* by   =(const float*)d_in[13];
    float* out=(float*)d_out;

    static bool attr_set=false;
    if (!attr_set){
        cudaFuncSetAttribute(hmm_kernel, cudaFuncAttributeMaxDynamicSharedMemorySize, HMM_SMEM);
        cudaFuncSetAttribute(gru_kernel, cudaFuncAttributeMaxDynamicSharedMemorySize, GRU_SMEM);
        attr_set=true;
    }

    gru_kernel<<<256,128,GRU_SMEM>>>(x,wih,whh,bih,bhh);
    hmm_kernel<<<256,256,HMM_SMEM>>>(x,lpi,lA,fc1w,fc1b,fc2w,fc2b);
    epi_kernel<<<4096,256>>>(Qseq,Wg,by,out);
}

// round 7
// speedup vs baseline: 1.8915x; 1.6284x over previous
#include <cuda_runtime.h>
#include <cuda_fp16.h>
#include <cstdint>
#include <math.h>

#define Bn 256
#define Tn 4096
#define BT (Bn*Tn)

__device__ unsigned g_h [BT];   // GRU hidden half2
__device__ float    g_gm[BT];   // gamma_1

static __device__ __forceinline__ __half2 tanh2(__half2 x){
    unsigned xi = *reinterpret_cast<unsigned*>(&x), ri;
    asm("tanh.approx.f16x2 %0, %1;" : "=r"(ri) : "r"(xi));
    return *reinterpret_cast<__half2*>(&ri);
}
static __device__ __forceinline__ float tanhap(float x){
    float y; asm("tanh.approx.f32 %0, %1;" : "=f"(y) : "f"(x)); return y;
}

// ============== K1: GRU — coalesced smem x, 16-step chunks ==============
// block 256 thr, 1 batch/block. thread c: chunk of 16 t (16-step warmup).
#define GRU_SX   12544            // 12288 + 256 pad
#define GRU_HB   4352             // 4096 + 256 pad
#define GRU_SMEM ((GRU_SX+GRU_HB)*4)

__global__ __launch_bounds__(256) void gru_kernel(
    const float* __restrict__ x,
    const float* __restrict__ wih, const float* __restrict__ whh,
    const float* __restrict__ bih, const float* __restrict__ bhh)
{
    extern __shared__ float sgru[];
    float*    sx = sgru;
    unsigned* hb = reinterpret_cast<unsigned*>(sgru + GRU_SX);
    int b = blockIdx.x, tid = threadIdx.x;

    // coalesced x load -> padded smem: sx[3t+(t>>4)]
    const float* xb = x + (size_t)b*Tn*3;
#pragma unroll
    for (int i = tid; i < 12288; i += 256) {
        int t = i/3;
        sx[i + (t>>4)] = xb[i];
    }

    // weights (r,z pre-halved, biases folded)
    float WI[18], CB[6];
#pragma unroll
    for (int j=0;j<4;j++){
#pragma unroll
        for (int d=0;d<3;d++) WI[j*3+d] = 0.5f*wih[j*3+d];
        CB[j] = 0.5f*(bih[j]+bhh[j]);
    }
#pragma unroll
    for (int j=4;j<6;j++){
#pragma unroll
        for (int d=0;d<3;d++) WI[j*3+d] = wih[j*3+d];
        CB[j] = bih[j];
    }
    float w[12];
#pragma unroll
    for (int i=0;i<12;i++) w[i]=whh[i];
    __half2 WRA=__floats2half2_rn(0.5f*w[0],0.5f*w[2]), WRB=__floats2half2_rn(0.5f*w[1],0.5f*w[3]);
    __half2 WZA=__floats2half2_rn(0.5f*w[4],0.5f*w[6]), WZB=__floats2half2_rn(0.5f*w[5],0.5f*w[7]);
    __half2 WNA=__floats2half2_rn(w[8],w[10]),          WNB=__floats2half2_rn(w[9],w[11]);
    __half2 BN =__floats2half2_rn(bhh[4],bhh[5]);
    const __half2 H05=__floats2half2_rn(0.5f,0.5f), HM05=__floats2half2_rn(-0.5f,-0.5f);
    __syncthreads();

    int c = tid;
    int tstart = (c==0) ? 0 : (c*16-16);
    int nwarm  = (c==0) ? 0 : 16;

    __half2 h = __floats2half2_rn(0.f,0.f);
#pragma unroll 4
    for (int s=0; s<32; s++){
        int tt = tstart + s;
        int a  = tt*3 + (tt>>4);
        float x0=sx[a], x1=sx[a+1], x2=sx[a+2];
        float gr0=fmaf(WI[0],x0,fmaf(WI[1],x1,fmaf(WI[2],x2,CB[0])));
        float gr1=fmaf(WI[3],x0,fmaf(WI[4],x1,fmaf(WI[5],x2,CB[1])));
        float gz0=fmaf(WI[6],x0,fmaf(WI[7],x1,fmaf(WI[8],x2,CB[2])));
        float gz1=fmaf(WI[9],x0,fmaf(WI[10],x1,fmaf(WI[11],x2,CB[3])));
        float gn0=fmaf(WI[12],x0,fmaf(WI[13],x1,fmaf(WI[14],x2,CB[4])));
        float gn1=fmaf(WI[15],x0,fmaf(WI[16],x1,fmaf(WI[17],x2,CB[5])));
        __half2 CR=__floats2half2_rn(gr0,gr1);
        __half2 CZ=__floats2half2_rn(gz0,gz1);
        __half2 CN=__floats2half2_rn(gn0,gn1);

        __half2 h0b=__half2half2(__low2half(h)), h1b=__half2half2(__high2half(h));
        __half2 aR=__hfma2(h0b,WRA,__hfma2(h1b,WRB,CR));
        __half2 aZ=__hfma2(h0b,WZA,__hfma2(h1b,WZB,CZ));
        __half2 GN=__hfma2(h0b,WNA,__hfma2(h1b,WNB,BN));
        __half2 tr=tanh2(aR), tz=tanh2(aZ);
        __half2 Ch=__hmul2(GN,H05);
        __half2 aN=__hfma2(tr,Ch,__hadd2(CN,Ch));
        __half2 tn=tanh2(aN);
        __half2 A =__hfma2(tz,HM05,H05);
        __half2 hh=__hmul2(h,H05);
        __half2 ZH=__hfma2(tz,hh,hh);
        h = __hfma2(tn,A,ZH);

        if (s>=nwarm && s<nwarm+16)
            hb[tt + (tt>>4)] = *reinterpret_cast<unsigned*>(&h);
    }
    __syncthreads();

    unsigned* hout = g_h + (size_t)b*Tn;
#pragma unroll
    for (int u=tid; u<4096; u+=256) hout[u] = hb[u + (u>>4)];
}

// ============== K2: emitter + HMM scan -> gamma1 ==============
// padded arrays TP(t) = t + (t>>4)
#define TP(t) ((t) + ((t)>>4))
#define HSQ   0
#define HSUF  4352
#define HSVF  8704
#define HSXE  13056
#define HSSUB 16128
#define HSP   17152
#define HSBF  17664
#define HSEB  17920
#define HMM_SMEM (18176*4)

__global__ __launch_bounds__(256) void hmm_kernel(
    const float* __restrict__ x,
    const float* __restrict__ lpi, const float* __restrict__ lAg,
    const float* __restrict__ fc1w,const float* __restrict__ fc1b,
    const float* __restrict__ fc2w,const float* __restrict__ fc2b)
{
    extern __shared__ float sm[];
    float* sq   = sm + HSQ;
    float* suf  = sm + HSUF;
    float* svf  = sm + HSVF;
    float* sxe  = sm + HSXE;
    float* sSub = sm + HSSUB;
    float* sP   = sm + HSP;
    float* sBf  = sm + HSBF;
    float* sEb  = sm + HSEB;

    int b = blockIdx.x, tid = threadIdx.x;

    float W1[24], B1[8], DW[8];
#pragma unroll
    for (int i=0;i<24;i++) W1[i]=fc1w[i];
#pragma unroll
    for (int i=0;i<8;i++){ B1[i]=fc1b[i]; DW[i]=fc2w[8+i]-fc2w[i]; }
    float db = fc2b[1]-fc2b[0];

    // emitter in 4 sections: coalesced x -> smem -> q
    for (int sec=0; sec<4; sec++){
        const float* xb = x + ((size_t)b*Tn + sec*1024)*3;
        __syncthreads();
#pragma unroll
        for (int i=tid;i<3072;i+=256) sxe[i]=xb[i];
        __syncthreads();
#pragma unroll
        for (int j=0;j<4;j++){
            int tl = tid + j*256;
            float x0=sxe[tl*3], x1=sxe[tl*3+1], x2=sxe[tl*3+2];
            float d = db;
#pragma unroll
            for (int k=0;k<8;k++){
                float u = fmaf(W1[k*3],x0,fmaf(W1[k*3+1],x1,fmaf(W1[k*3+2],x2,B1[k])));
                d = fmaf(DW[k], tanhap(u), d);
            }
            int t = sec*1024 + tl;
            sq[TP(t)] = __expf(d);
        }
    }

    float l00=lAg[0],l01=lAg[1],l10=lAg[2],l11=lAg[3];
    float m0=fmaxf(l00,l01), m1=fmaxf(l10,l11);
    float e00=__expf(l00-m0), e01=__expf(l01-m0), e10=__expf(l10-m1), e11=__expf(l11-m1);
    float i0=__fdividef(1.f,e00+e01), i1=__fdividef(1.f,e10+e11);
    float a00=e00*i0, a01=e01*i0, a10=e10*i1, a11=e11*i1;
    float p1=__expf(lpi[1]-lpi[0]);
    __syncthreads();

    // stage 1a: 16-step sub-products (256 of them)
    {
        int ts = tid*16, te = ts+16;
        if (tid==0) ts = 1;
        float p00=1.f,p01=0.f,p10=0.f,p11=1.f;
        for (int t=ts;t<te;t++){
            float qv=sq[TP(t)], qa01=a01*qv, qa11=a11*qv;
            float n00=fmaf(p01,a10,p00*a00), n01=fmaf(p01,qa11,p00*qa01);
            float n10=fmaf(p11,a10,p10*a00), n11=fmaf(p11,qa11,p10*qa01);
            p00=n00;p01=n01;p10=n10;p11=n11;
        }
        float s=__fdividef(1.f,p00+p01+p10+p11);
        sSub[tid*4]=p00*s; sSub[tid*4+1]=p01*s; sSub[tid*4+2]=p10*s; sSub[tid*4+3]=p11*s;
    }
    __syncthreads();

    // stage 1b: combine 2 subs -> 128 chunk products (32 t each)
    if (tid < 128) {
        const float* S0 = sSub + tid*8;
        const float* S1 = S0 + 4;
        float p00=S0[0],p01=S0[1],p10=S0[2],p11=S0[3];
        float n00=fmaf(p01,S1[2],p00*S1[0]), n01=fmaf(p01,S1[3],p00*S1[1]);
        float n10=fmaf(p11,S1[2],p10*S1[0]), n11=fmaf(p11,S1[3],p10*S1[1]);
        float s=__fdividef(1.f,n00+n01+n10+n11);
        sP[tid*4]=n00*s; sP[tid*4+1]=n01*s; sP[tid*4+2]=n10*s; sP[tid*4+3]=n11*s;
    }
    __syncthreads();

    // stage 2: boundary chains (127 steps each)
    if (tid == 0) {
        float u=1.f, v=p1*sq[TP(0)];
        sBf[0]=u; sBf[1]=v;
        for (int c=0;c<127;c++){
            const float* P=sP+c*4;
            float nu=fmaf(v,P[2],u*P[0]);
            float nv=fmaf(v,P[3],u*P[1]);
            u=nu; v=nv;
            if ((c&7)==7){ float is=__fdividef(1.f,u+v); u*=is; v*=is; }
            sBf[(c+1)*2]=u; sBf[(c+1)*2+1]=v;
        }
    } else if (tid == 32) {
        float u=1.f, v=1.f;
        sEb[127*2]=1.f; sEb[127*2+1]=1.f;
        for (int c=126;c>=0;c--){
            const float* P=sP+(c+1)*4;
            float nu=fmaf(P[1],v,P[0]*u);
            float nv=fmaf(P[3],v,P[2]*u);
            u=nu; v=nv;
            if ((c&7)==0){ float is=__fdividef(1.f,u+v); u*=is; v*=is; }
            sEb[c*2]=u; sEb[c*2+1]=v;
        }
    }
    __syncthreads();

    // stage 3a: forward replay (128 chunks of 32)
    if (tid < 128) {
        int c=tid;
        float u,v; int ts;
        if (c==0){ u=1.f; v=p1*sq[TP(0)]; suf[TP(0)]=u; svf[TP(0)]=v; ts=1; }
        else     { u=sBf[c*2]; v=sBf[c*2+1]; ts=c*32; }
        int te=c*32+31;
        for (int t=ts;t<=te;t++){
            float qv=sq[TP(t)];
            float nu=fmaf(a10,v,a00*u);
            float nv=qv*fmaf(a11,v,a01*u);
            u=nu; v=nv;
            if ((t&7)==7){ float is=__fdividef(1.f,u+v); u*=is; v*=is; }
            suf[TP(t)]=u; svf[TP(t)]=v;
        }
    }
    __syncthreads();

    // stage 3b: backward replay; overwrite suf[t] with gamma1
    if (tid < 128) {
        int c=tid;
        float u=sEb[c*2], v=sEb[c*2+1];
        int ts=c*32, te=c*32+31;
        {
            float n0=suf[TP(te)]*u, n1=svf[TP(te)]*v;
            suf[TP(te)] = __fdividef(n1, n0+n1);
        }
        for (int t=te-1;t>=ts;t--){
            float w=sq[TP(t+1)]*v;
            float nu=fmaf(a01,w,a00*u);
            float nv=fmaf(a11,w,a10*u);
            u=nu; v=nv;
            if ((t&7)==0){ float is=__fdividef(1.f,u+v); u*=is; v*=is; }
            float n0=suf[TP(t)]*u, n1=svf[TP(t)]*v;
            suf[TP(t)] = __fdividef(n1, n0+n1);
        }
    }
    __syncthreads();

    // gamma1 out (coalesced)
    float* gmp = g_gm + (size_t)b*Tn;
#pragma unroll
    for (int t=tid; t<Tn; t+=256) gmp[t] = suf[TP(t)];
}

// ============== K3: epilogue — smem-staged coalesced I/O ==============
__global__ __launch_bounds__(256) void epi_kernel(
    const float* __restrict__ Qseq,
    const float* __restrict__ Wgp, const float* __restrict__ byp,
    float* __restrict__ out)
{
    __shared__ float sQ[2560];
    __shared__ float sG[1280];
    int tid = threadIdx.x;
    size_t base = (size_t)blockIdx.x*256;

    const float* Qb = Qseq + base*10;
#pragma unroll
    for (int i=tid;i<2560;i+=256) sQ[i]=Qb[i];

    float WG[20], BY[4];
#pragma unroll
    for (int i=0;i<20;i++) WG[i]=Wgp[i];
#pragma unroll
    for (int i=0;i<4;i++) BY[i]=byp[i];
    __syncthreads();

    size_t idx = base + tid;
    float gm1 = g_gm[idx], gm0 = 1.f - gm1;
    float lg0 = __logf(gm0), lg1 = __logf(gm1);

    unsigned hv = g_h[idx];
    __half2 h2 = *reinterpret_cast<__half2*>(&hv);
    float h0=__low2float(h2), h1=__high2float(h2);

    float gk[2][5];
#pragma unroll
    for (int k=0;k<2;k++){
        float wv[5], mx=-1e30f;
#pragma unroll
        for (int a=0;a<5;a++){ wv[a]=fmaf(h0,WG[k*10+a],h1*WG[k*10+5+a]); mx=fmaxf(mx,wv[a]); }
        float s=0.f;
#pragma unroll
        for (int a=0;a<5;a++){ wv[a]=__expf(wv[a]-mx); s+=wv[a]; }
        float is=__fdividef(1.f,s);
#pragma unroll
        for (int a=0;a<5;a++) gk[k][a]=wv[a]*is;
    }
    float gv[5];
#pragma unroll
    for (int a=0;a<5;a++) gv[a]=fmaf(gm0,gk[0][a],gm1*gk[1][a]);

    float V0=fmaf(gm0,BY[0],gm1*BY[2]);
    float V1=fmaf(gm0,BY[1],gm1*BY[3]);
#pragma unroll
    for (int a=0;a<5;a++){
        float qx=sQ[tid*10+a*2], qy=sQ[tid*10+a*2+1];
        V0=fmaf(gv[a],qx,V0);
        V1=fmaf(gv[a],qy,V1);
        sG[tid*5+a]=gv[a];
    }
    float mv=fmaxf(V0,V1);
    float lse=mv+__logf(__expf(V0-mv)+__expf(V1-mv));

    const size_t OFF1=(size_t)BT*2, OFF2=(size_t)BT*7;
    reinterpret_cast<float2*>(out)[idx]              = make_float2(V0-lse, V1-lse);
    reinterpret_cast<float2*>(out+OFF2)[idx]         = make_float2(lg0, lg1);
    __syncthreads();
    float* go = out + OFF1 + base*5;
#pragma unroll
    for (int i=tid;i<1280;i+=256) go[i]=sG[i];
}

// ========================= launch =========================
extern "C" void kernel_launch(void* const* d_in, const int* in_sizes, int n_in,
                              void* d_out, int out_size)
{
    const float* x    =(const float*)d_in[0];
    const float* Qseq =(const float*)d_in[1];
    const float* lpi  =(const float*)d_in[2];
    const float* lA   =(const float*)d_in[3];
    const float* fc1w =(const float*)d_in[4];
    const float* fc1b =(const float*)d_in[5];
    const float* fc2w =(const float*)d_in[6];
    const float* fc2b =(const float*)d_in[7];
    const float* wih  =(const float*)d_in[8];
    const float* whh  =(const float*)d_in[9];
    const float* bih  =(const float*)d_in[10];
    const float* bhh  =(const float*)d_in[11];
    const float* Wg   =(const float*)d_in[12];
    const float* by   =(const float*)d_in[13];
    float* out=(float*)d_out;

    static bool attr_set=false;
    if (!attr_set){
        cudaFuncSetAttribute(hmm_kernel, cudaFuncAttributeMaxDynamicSharedMemorySize, HMM_SMEM);
        cudaFuncSetAttribute(gru_kernel, cudaFuncAttributeMaxDynamicSharedMemorySize, GRU_SMEM);
        attr_set=true;
    }

    gru_kernel<<<256,256,GRU_SMEM>>>(x,wih,whh,bih,bhh);
    hmm_kernel<<<256,256,HMM_SMEM>>>(x,lpi,lA,fc1w,fc1b,fc2w,fc2b);
    epi_kernel<<<4096,256>>>(Qseq,Wg,by,out);
}